// round 6
// baseline (speedup 1.0000x reference)
#include <cuda_runtime.h>

// Problem dims
constexpr int BQ = 512;   // batch
constexpr int TQ = 512;   // time
constexpr int IQ = 64;    // layer0 input
constexpr int HQ = 128;   // hidden
constexpr int GQ = 384;   // 3*H, gate order (r, z, n)

// Scratch: gi pre-activations [B, T, 3H] and layer hidden history [B, T, H].
// __device__ globals are the sanctioned scratch mechanism (no cudaMalloc).
__device__ float g_gi[(size_t)BQ * TQ * GQ];    // ~402 MB, reused by both layers
__device__ float g_hist[(size_t)BQ * TQ * HQ];  // ~134 MB, h1 then h2 history

// ---------------------------------------------------------------------------
// Phase GEMM: gi[m, g] = sum_k X[m, k] * W[g, k] + bias[g]
// m = b*T + t, M = B*T = 262144. One thread per row m; X row held in
// registers, W broadcast from SMEM (uniform address per warp -> LDS broadcast).
// Writes float4 (4 consecutive g) -> 16B granules, 2x sector inflation max.
// ---------------------------------------------------------------------------
template <int K>
__global__ __launch_bounds__(256, 1) void gi_gemm(
    const float* __restrict__ X, const float* __restrict__ W,
    const float* __restrict__ bias, float* __restrict__ gi)
{
    extern __shared__ float sm[];
    float* Ws    = sm;            // [G][K], row-major copy of W
    float* biasS = sm + GQ * K;   // [G]

    const int tid = threadIdx.x;
    for (int i = tid; i < GQ * K; i += 256) Ws[i] = W[i];
    for (int i = tid; i < GQ; i += 256) biasS[i] = bias[i];
    __syncthreads();

    const int m = blockIdx.x * 256 + tid;

    // Load this row of X into registers
    float4 xr[K / 4];
    const float4* X4 = reinterpret_cast<const float4*>(X) + (size_t)m * (K / 4);
#pragma unroll
    for (int k4 = 0; k4 < K / 4; ++k4) xr[k4] = X4[k4];

    const float4* Ws4 = reinterpret_cast<const float4*>(Ws);
    float4* gi4 = reinterpret_cast<float4*>(gi) + (size_t)m * (GQ / 4);

    for (int n4 = 0; n4 < GQ / 4; ++n4) {
        float a0 = biasS[4 * n4 + 0];
        float a1 = biasS[4 * n4 + 1];
        float a2 = biasS[4 * n4 + 2];
        float a3 = biasS[4 * n4 + 3];
#pragma unroll
        for (int k4 = 0; k4 < K / 4; ++k4) {
            const float4 x  = xr[k4];
            const float4 w0 = Ws4[(size_t)(4 * n4 + 0) * (K / 4) + k4];
            const float4 w1 = Ws4[(size_t)(4 * n4 + 1) * (K / 4) + k4];
            const float4 w2 = Ws4[(size_t)(4 * n4 + 2) * (K / 4) + k4];
            const float4 w3 = Ws4[(size_t)(4 * n4 + 3) * (K / 4) + k4];
            a0 = fmaf(x.x, w0.x, a0); a0 = fmaf(x.y, w0.y, a0);
            a0 = fmaf(x.z, w0.z, a0); a0 = fmaf(x.w, w0.w, a0);
            a1 = fmaf(x.x, w1.x, a1); a1 = fmaf(x.y, w1.y, a1);
            a1 = fmaf(x.z, w1.z, a1); a1 = fmaf(x.w, w1.w, a1);
            a2 = fmaf(x.x, w2.x, a2); a2 = fmaf(x.y, w2.y, a2);
            a2 = fmaf(x.z, w2.z, a2); a2 = fmaf(x.w, w2.w, a2);
            a3 = fmaf(x.x, w3.x, a3); a3 = fmaf(x.y, w3.y, a3);
            a3 = fmaf(x.z, w3.z, a3); a3 = fmaf(x.w, w3.w, a3);
        }
        float4 o; o.x = a0; o.y = a1; o.z = a2; o.w = a3;
        gi4[n4] = o;
    }
}

// ---------------------------------------------------------------------------
// Fast gate nonlinearities (fp32 in/out, MUFU-based)
// ---------------------------------------------------------------------------
__device__ __forceinline__ float sigmoid_fast(float x) {
    return __fdividef(1.0f, 1.0f + __expf(-x));
}
__device__ __forceinline__ float tanh_fast(float x) {
    x = fminf(fmaxf(x, -15.0f), 15.0f);
    const float e = __expf(2.0f * x);
    return __fdividef(e - 1.0f, e + 1.0f);
}

// ---------------------------------------------------------------------------
// Persistent recurrence kernel. Grid = 128 CTAs, each owns 4 batch rows —
// NO inter-CTA sync needed. W_hh lives in SMEM as float4 per (k4, g):
//   Wsv[k4*G + g] = (W[g][4k4], W[g][4k4+1], W[g][4k4+2], W[g][4k4+3])
// Thread g computes gh[r][g] for r=0..3; h[r][k] read as float4 broadcasts.
// Gate-phase gi operands are prefetched at loop top (hidden behind the GEMM).
// ---------------------------------------------------------------------------
__global__ __launch_bounds__(384, 1) void gru_rec(
    const float* __restrict__ gi, const float* __restrict__ Whh,
    const float* __restrict__ bhh, float* __restrict__ hist)
{
    extern __shared__ float sm[];
    float4* Wsv = reinterpret_cast<float4*>(sm);        // [H/4][G] float4
    float*  hS  = sm + HQ * GQ;                         // [4][H]
    float*  ghS = hS + 4 * HQ;                          // [4][G]

    const int tid = threadIdx.x;   // 0..383
    const int b0  = blockIdx.x * 4;

    // Stage W_hh (transposed, k4-vectorized). One-time.
    for (int i = tid; i < (HQ / 4) * GQ; i += 384) {
        const int k4 = i / GQ;
        const int g  = i - k4 * GQ;
        float4 w;
        w.x = Whh[g * HQ + 4 * k4 + 0];
        w.y = Whh[g * HQ + 4 * k4 + 1];
        w.z = Whh[g * HQ + 4 * k4 + 2];
        w.w = Whh[g * HQ + 4 * k4 + 3];
        Wsv[i] = w;
    }
    for (int i = tid; i < 4 * HQ; i += 384) hS[i] = 0.0f;

    const float bg = bhh[tid];     // accumulator seed: b_hh baked into gh

    // Gate-phase work mapping: item0 = tid covers rows 0..2; threads <128
    // additionally cover row 3.
    const int  row0 = tid >> 7;
    const int  j0   = tid & 127;
    const bool two  = (tid < 128);

    __syncthreads();

    const float4* hS4 = reinterpret_cast<const float4*>(hS);
    const int g = tid;

    for (int t = 0; t < TQ; ++t) {
        // ---- prefetch gate gi operands (latency hidden behind GEMM) ----
        const float* giA = gi + ((size_t)(b0 + row0) * TQ + t) * GQ;
        const float gir0 = giA[j0];
        const float giz0 = giA[j0 + 128];
        const float gin0 = giA[j0 + 256];
        float gir1 = 0.f, giz1 = 0.f, gin1 = 0.f;
        if (two) {
            const float* giB = gi + ((size_t)(b0 + 3) * TQ + t) * GQ;
            gir1 = giB[tid]; giz1 = giB[tid + 128]; gin1 = giB[tid + 256];
        }

        // ---- gh[r][g] = b_hh[g] + sum_k h[r][k] * W_hh[g][k] ----
        float a0 = bg, a1 = bg, a2 = bg, a3 = bg;
#pragma unroll
        for (int k4 = 0; k4 < HQ / 4; ++k4) {
            const float4 w  = Wsv[k4 * GQ + g];
            const float4 h0 = hS4[0 * (HQ / 4) + k4];
            const float4 h1 = hS4[1 * (HQ / 4) + k4];
            const float4 h2 = hS4[2 * (HQ / 4) + k4];
            const float4 h3 = hS4[3 * (HQ / 4) + k4];
            a0 = fmaf(h0.x, w.x, a0); a0 = fmaf(h0.y, w.y, a0);
            a0 = fmaf(h0.z, w.z, a0); a0 = fmaf(h0.w, w.w, a0);
            a1 = fmaf(h1.x, w.x, a1); a1 = fmaf(h1.y, w.y, a1);
            a1 = fmaf(h1.z, w.z, a1); a1 = fmaf(h1.w, w.w, a1);
            a2 = fmaf(h2.x, w.x, a2); a2 = fmaf(h2.y, w.y, a2);
            a2 = fmaf(h2.z, w.z, a2); a2 = fmaf(h2.w, w.w, a2);
            a3 = fmaf(h3.x, w.x, a3); a3 = fmaf(h3.y, w.y, a3);
            a3 = fmaf(h3.z, w.z, a3); a3 = fmaf(h3.w, w.w, a3);
        }
        ghS[0 * GQ + g] = a0;
        ghS[1 * GQ + g] = a1;
        ghS[2 * GQ + g] = a2;
        ghS[3 * GQ + g] = a3;
        __syncthreads();   // ghS visible; all hS reads of this step done

        // ---- gates + h update ----
        {
            const float ghr  = ghS[row0 * GQ + j0];
            const float ghz  = ghS[row0 * GQ + j0 + 128];
            const float ghn  = ghS[row0 * GQ + j0 + 256];
            const float hold = hS[row0 * HQ + j0];
            const float r = sigmoid_fast(gir0 + ghr);
            const float z = sigmoid_fast(giz0 + ghz);
            const float n = tanh_fast(gin0 + r * ghn);
            const float hn = (1.0f - z) * n + z * hold;
            hS[row0 * HQ + j0] = hn;
            hist[((size_t)(b0 + row0) * TQ + t) * HQ + j0] = hn;
        }
        if (two) {
            const float ghr  = ghS[3 * GQ + tid];
            const float ghz  = ghS[3 * GQ + tid + 128];
            const float ghn  = ghS[3 * GQ + tid + 256];
            const float hold = hS[3 * HQ + tid];
            const float r = sigmoid_fast(gir1 + ghr);
            const float z = sigmoid_fast(giz1 + ghz);
            const float n = tanh_fast(gin1 + r * ghn);
            const float hn = (1.0f - z) * n + z * hold;
            hS[3 * HQ + tid] = hn;
            hist[((size_t)(b0 + 3) * TQ + t) * HQ + tid] = hn;
        }
        __syncthreads();   // new h visible before next step's GEMM
    }
}

// ---------------------------------------------------------------------------
// Final FC: out[b] = dot(h2[b, T-1, :], W_fc[0, :]) + b_fc[0]
// ---------------------------------------------------------------------------
__global__ void fc_kernel(const float* __restrict__ hist,
                          const float* __restrict__ Wfc,
                          const float* __restrict__ bfc,
                          float* __restrict__ out)
{
    const int b   = blockIdx.x;
    const int tid = threadIdx.x;   // 128
    float v = hist[((size_t)b * TQ + (TQ - 1)) * HQ + tid] * Wfc[tid];
#pragma unroll
    for (int o = 16; o > 0; o >>= 1) v += __shfl_xor_sync(0xffffffffu, v, o);
    __shared__ float red[4];
    if ((tid & 31) == 0) red[tid >> 5] = v;
    __syncthreads();
    if (tid == 0) out[b] = red[0] + red[1] + red[2] + red[3] + bfc[0];
}

// ---------------------------------------------------------------------------
// kernel_launch: 5 launches, all graph-capturable, no allocations.
// ---------------------------------------------------------------------------
extern "C" void kernel_launch(void* const* d_in, const int* in_sizes, int n_in,
                              void* d_out, int out_size)
{
    const float* x     = (const float*)d_in[0];
    const float* W_ih0 = (const float*)d_in[1];
    const float* W_hh0 = (const float*)d_in[2];
    const float* b_ih0 = (const float*)d_in[3];
    const float* b_hh0 = (const float*)d_in[4];
    const float* W_ih1 = (const float*)d_in[5];
    const float* W_hh1 = (const float*)d_in[6];
    const float* b_ih1 = (const float*)d_in[7];
    const float* b_hh1 = (const float*)d_in[8];
    const float* W_fc  = (const float*)d_in[9];
    const float* b_fc  = (const float*)d_in[10];
    float* out = (float*)d_out;

    float* gi_ptr   = nullptr;
    float* hist_ptr = nullptr;
    cudaGetSymbolAddress((void**)&gi_ptr, g_gi);
    cudaGetSymbolAddress((void**)&hist_ptr, g_hist);

    constexpr int SMEM_GI64  = GQ * IQ * 4 + GQ * 4;   //  99840 B
    constexpr int SMEM_GI128 = GQ * HQ * 4 + GQ * 4;   // 198144 B
    constexpr int SMEM_REC   = HQ * GQ * 4 + 4 * HQ * 4 + 4 * GQ * 4; // 204800 B

    cudaFuncSetAttribute(gi_gemm<IQ>, cudaFuncAttributeMaxDynamicSharedMemorySize, SMEM_GI64);
    cudaFuncSetAttribute(gi_gemm<HQ>, cudaFuncAttributeMaxDynamicSharedMemorySize, SMEM_GI128);
    cudaFuncSetAttribute(gru_rec,     cudaFuncAttributeMaxDynamicSharedMemorySize, SMEM_REC);

    const int M_BLOCKS = (BQ * TQ) / 256;  // 1024

    // Layer 0
    gi_gemm<IQ><<<M_BLOCKS, 256, SMEM_GI64>>>(x, W_ih0, b_ih0, gi_ptr);
    gru_rec<<<BQ / 4, 384, SMEM_REC>>>(gi_ptr, W_hh0, b_hh0, hist_ptr);
    // Layer 1 (gi buffer reused; hist overwritten with h2 after gi1 is built)
    gi_gemm<HQ><<<M_BLOCKS, 256, SMEM_GI128>>>(hist_ptr, W_ih1, b_ih1, gi_ptr);
    gru_rec<<<BQ / 4, 384, SMEM_REC>>>(gi_ptr, W_hh1, b_hh1, hist_ptr);
    // FC head
    fc_kernel<<<BQ, 128>>>(hist_ptr, W_fc, b_fc, out);
}

// round 9
// speedup vs baseline: 1.0026x; 1.0026x over previous
#include <cuda_runtime.h>

// Problem dims
constexpr int BQ = 512;   // batch
constexpr int TQ = 512;   // time
constexpr int IQ = 64;    // layer0 input
constexpr int HQ = 128;   // hidden
constexpr int GQ = 384;   // 3*H, gate order (r, z, n)

// Scratch: gi pre-activations [B, T, 3H] and layer hidden history [B, T, H].
// __device__ globals are the sanctioned scratch mechanism (no cudaMalloc).
__device__ float g_gi[(size_t)BQ * TQ * GQ];    // ~402 MB, reused by both layers
__device__ float g_hist[(size_t)BQ * TQ * HQ];  // ~134 MB, h1 then h2 history

// ---------------------------------------------------------------------------
// Phase GEMM: gi[m, g] = sum_k X[m, k] * W[g, k] + bias[g]
// m = b*T + t, M = B*T = 262144. One thread per row m; X row held in
// registers, W broadcast from SMEM (uniform address per warp -> LDS broadcast).
// Writes float4 (4 consecutive g) -> 16B granules, 2x sector inflation max.
// ---------------------------------------------------------------------------
template <int K>
__global__ __launch_bounds__(256, 1) void gi_gemm(
    const float* __restrict__ X, const float* __restrict__ W,
    const float* __restrict__ bias, float* __restrict__ gi)
{
    extern __shared__ float sm[];
    float* Ws    = sm;            // [G][K], row-major copy of W
    float* biasS = sm + GQ * K;   // [G]

    const int tid = threadIdx.x;
    for (int i = tid; i < GQ * K; i += 256) Ws[i] = W[i];
    for (int i = tid; i < GQ; i += 256) biasS[i] = bias[i];
    __syncthreads();

    const int m = blockIdx.x * 256 + tid;

    // Load this row of X into registers
    float4 xr[K / 4];
    const float4* X4 = reinterpret_cast<const float4*>(X) + (size_t)m * (K / 4);
#pragma unroll
    for (int k4 = 0; k4 < K / 4; ++k4) xr[k4] = X4[k4];

    const float4* Ws4 = reinterpret_cast<const float4*>(Ws);
    float4* gi4 = reinterpret_cast<float4*>(gi) + (size_t)m * (GQ / 4);

    for (int n4 = 0; n4 < GQ / 4; ++n4) {
        float a0 = biasS[4 * n4 + 0];
        float a1 = biasS[4 * n4 + 1];
        float a2 = biasS[4 * n4 + 2];
        float a3 = biasS[4 * n4 + 3];
#pragma unroll
        for (int k4 = 0; k4 < K / 4; ++k4) {
            const float4 x  = xr[k4];
            const float4 w0 = Ws4[(size_t)(4 * n4 + 0) * (K / 4) + k4];
            const float4 w1 = Ws4[(size_t)(4 * n4 + 1) * (K / 4) + k4];
            const float4 w2 = Ws4[(size_t)(4 * n4 + 2) * (K / 4) + k4];
            const float4 w3 = Ws4[(size_t)(4 * n4 + 3) * (K / 4) + k4];
            a0 = fmaf(x.x, w0.x, a0); a0 = fmaf(x.y, w0.y, a0);
            a0 = fmaf(x.z, w0.z, a0); a0 = fmaf(x.w, w0.w, a0);
            a1 = fmaf(x.x, w1.x, a1); a1 = fmaf(x.y, w1.y, a1);
            a1 = fmaf(x.z, w1.z, a1); a1 = fmaf(x.w, w1.w, a1);
            a2 = fmaf(x.x, w2.x, a2); a2 = fmaf(x.y, w2.y, a2);
            a2 = fmaf(x.z, w2.z, a2); a2 = fmaf(x.w, w2.w, a2);
            a3 = fmaf(x.x, w3.x, a3); a3 = fmaf(x.y, w3.y, a3);
            a3 = fmaf(x.z, w3.z, a3); a3 = fmaf(x.w, w3.w, a3);
        }
        float4 o; o.x = a0; o.y = a1; o.z = a2; o.w = a3;
        gi4[n4] = o;
    }
}

// ---------------------------------------------------------------------------
// Fast gate nonlinearities (fp32 in/out, MUFU-based)
// ---------------------------------------------------------------------------
__device__ __forceinline__ float sigmoid_fast(float x) {
    return __fdividef(1.0f, 1.0f + __expf(-x));
}
__device__ __forceinline__ float tanh_fast(float x) {
    x = fminf(fmaxf(x, -15.0f), 15.0f);
    const float e = __expf(2.0f * x);
    return __fdividef(e - 1.0f, e + 1.0f);
}

// ---------------------------------------------------------------------------
// Persistent recurrence kernel. Grid = 128 CTAs, each owns 4 batch rows —
// NO inter-CTA sync needed. W_hh lives in SMEM as float4 per (k4, g):
//   Wsv[k4*G + g] = (W[g][4k4], W[g][4k4+1], W[g][4k4+2], W[g][4k4+3])
// Thread g computes gh[r][g] for r=0..3; h[r][k] read as float4 broadcasts.
// Gate-phase gi operands are prefetched at loop top (hidden behind the GEMM).
// ---------------------------------------------------------------------------
__global__ __launch_bounds__(384, 1) void gru_rec(
    const float* __restrict__ gi, const float* __restrict__ Whh,
    const float* __restrict__ bhh, float* __restrict__ hist)
{
    extern __shared__ float sm[];
    float4* Wsv = reinterpret_cast<float4*>(sm);        // [H/4][G] float4
    float*  hS  = sm + HQ * GQ;                         // [4][H]
    float*  ghS = hS + 4 * HQ;                          // [4][G]

    const int tid = threadIdx.x;   // 0..383
    const int b0  = blockIdx.x * 4;

    // Stage W_hh (transposed, k4-vectorized). One-time.
    for (int i = tid; i < (HQ / 4) * GQ; i += 384) {
        const int k4 = i / GQ;
        const int g  = i - k4 * GQ;
        float4 w;
        w.x = Whh[g * HQ + 4 * k4 + 0];
        w.y = Whh[g * HQ + 4 * k4 + 1];
        w.z = Whh[g * HQ + 4 * k4 + 2];
        w.w = Whh[g * HQ + 4 * k4 + 3];
        Wsv[i] = w;
    }
    for (int i = tid; i < 4 * HQ; i += 384) hS[i] = 0.0f;

    const float bg = bhh[tid];     // accumulator seed: b_hh baked into gh

    // Gate-phase work mapping: item0 = tid covers rows 0..2; threads <128
    // additionally cover row 3.
    const int  row0 = tid >> 7;
    const int  j0   = tid & 127;
    const bool two  = (tid < 128);

    __syncthreads();

    const float4* hS4 = reinterpret_cast<const float4*>(hS);
    const int g = tid;

    for (int t = 0; t < TQ; ++t) {
        // ---- prefetch gate gi operands (latency hidden behind GEMM) ----
        const float* giA = gi + ((size_t)(b0 + row0) * TQ + t) * GQ;
        const float gir0 = giA[j0];
        const float giz0 = giA[j0 + 128];
        const float gin0 = giA[j0 + 256];
        float gir1 = 0.f, giz1 = 0.f, gin1 = 0.f;
        if (two) {
            const float* giB = gi + ((size_t)(b0 + 3) * TQ + t) * GQ;
            gir1 = giB[tid]; giz1 = giB[tid + 128]; gin1 = giB[tid + 256];
        }

        // ---- gh[r][g] = b_hh[g] + sum_k h[r][k] * W_hh[g][k] ----
        float a0 = bg, a1 = bg, a2 = bg, a3 = bg;
#pragma unroll
        for (int k4 = 0; k4 < HQ / 4; ++k4) {
            const float4 w  = Wsv[k4 * GQ + g];
            const float4 h0 = hS4[0 * (HQ / 4) + k4];
            const float4 h1 = hS4[1 * (HQ / 4) + k4];
            const float4 h2 = hS4[2 * (HQ / 4) + k4];
            const float4 h3 = hS4[3 * (HQ / 4) + k4];
            a0 = fmaf(h0.x, w.x, a0); a0 = fmaf(h0.y, w.y, a0);
            a0 = fmaf(h0.z, w.z, a0); a0 = fmaf(h0.w, w.w, a0);
            a1 = fmaf(h1.x, w.x, a1); a1 = fmaf(h1.y, w.y, a1);
            a1 = fmaf(h1.z, w.z, a1); a1 = fmaf(h1.w, w.w, a1);
            a2 = fmaf(h2.x, w.x, a2); a2 = fmaf(h2.y, w.y, a2);
            a2 = fmaf(h2.z, w.z, a2); a2 = fmaf(h2.w, w.w, a2);
            a3 = fmaf(h3.x, w.x, a3); a3 = fmaf(h3.y, w.y, a3);
            a3 = fmaf(h3.z, w.z, a3); a3 = fmaf(h3.w, w.w, a3);
        }
        ghS[0 * GQ + g] = a0;
        ghS[1 * GQ + g] = a1;
        ghS[2 * GQ + g] = a2;
        ghS[3 * GQ + g] = a3;
        __syncthreads();   // ghS visible; all hS reads of this step done

        // ---- gates + h update ----
        {
            const float ghr  = ghS[row0 * GQ + j0];
            const float ghz  = ghS[row0 * GQ + j0 + 128];
            const float ghn  = ghS[row0 * GQ + j0 + 256];
            const float hold = hS[row0 * HQ + j0];
            const float r = sigmoid_fast(gir0 + ghr);
            const float z = sigmoid_fast(giz0 + ghz);
            const float n = tanh_fast(gin0 + r * ghn);
            const float hn = (1.0f - z) * n + z * hold;
            hS[row0 * HQ + j0] = hn;
            hist[((size_t)(b0 + row0) * TQ + t) * HQ + j0] = hn;
        }
        if (two) {
            const float ghr  = ghS[3 * GQ + tid];
            const float ghz  = ghS[3 * GQ + tid + 128];
            const float ghn  = ghS[3 * GQ + tid + 256];
            const float hold = hS[3 * HQ + tid];
            const float r = sigmoid_fast(gir1 + ghr);
            const float z = sigmoid_fast(giz1 + ghz);
            const float n = tanh_fast(gin1 + r * ghn);
            const float hn = (1.0f - z) * n + z * hold;
            hS[3 * HQ + tid] = hn;
            hist[((size_t)(b0 + 3) * TQ + t) * HQ + tid] = hn;
        }
        __syncthreads();   // new h visible before next step's GEMM
    }
}

// ---------------------------------------------------------------------------
// Final FC: out[b] = dot(h2[b, T-1, :], W_fc[0, :]) + b_fc[0]
// ---------------------------------------------------------------------------
__global__ void fc_kernel(const float* __restrict__ hist,
                          const float* __restrict__ Wfc,
                          const float* __restrict__ bfc,
                          float* __restrict__ out)
{
    const int b   = blockIdx.x;
    const int tid = threadIdx.x;   // 128
    float v = hist[((size_t)b * TQ + (TQ - 1)) * HQ + tid] * Wfc[tid];
#pragma unroll
    for (int o = 16; o > 0; o >>= 1) v += __shfl_xor_sync(0xffffffffu, v, o);
    __shared__ float red[4];
    if ((tid & 31) == 0) red[tid >> 5] = v;
    __syncthreads();
    if (tid == 0) out[b] = red[0] + red[1] + red[2] + red[3] + bfc[0];
}

// ---------------------------------------------------------------------------
// kernel_launch: 5 launches, all graph-capturable, no allocations.
// ---------------------------------------------------------------------------
extern "C" void kernel_launch(void* const* d_in, const int* in_sizes, int n_in,
                              void* d_out, int out_size)
{
    const float* x     = (const float*)d_in[0];
    const float* W_ih0 = (const float*)d_in[1];
    const float* W_hh0 = (const float*)d_in[2];
    const float* b_ih0 = (const float*)d_in[3];
    const float* b_hh0 = (const float*)d_in[4];
    const float* W_ih1 = (const float*)d_in[5];
    const float* W_hh1 = (const float*)d_in[6];
    const float* b_ih1 = (const float*)d_in[7];
    const float* b_hh1 = (const float*)d_in[8];
    const float* W_fc  = (const float*)d_in[9];
    const float* b_fc  = (const float*)d_in[10];
    float* out = (float*)d_out;

    float* gi_ptr   = nullptr;
    float* hist_ptr = nullptr;
    cudaGetSymbolAddress((void**)&gi_ptr, g_gi);
    cudaGetSymbolAddress((void**)&hist_ptr, g_hist);

    constexpr int SMEM_GI64  = GQ * IQ * 4 + GQ * 4;   //  99840 B
    constexpr int SMEM_GI128 = GQ * HQ * 4 + GQ * 4;   // 198144 B
    constexpr int SMEM_REC   = HQ * GQ * 4 + 4 * HQ * 4 + 4 * GQ * 4; // 204800 B

    cudaFuncSetAttribute(gi_gemm<IQ>, cudaFuncAttributeMaxDynamicSharedMemorySize, SMEM_GI64);
    cudaFuncSetAttribute(gi_gemm<HQ>, cudaFuncAttributeMaxDynamicSharedMemorySize, SMEM_GI128);
    cudaFuncSetAttribute(gru_rec,     cudaFuncAttributeMaxDynamicSharedMemorySize, SMEM_REC);

    const int M_BLOCKS = (BQ * TQ) / 256;  // 1024

    // Layer 0
    gi_gemm<IQ><<<M_BLOCKS, 256, SMEM_GI64>>>(x, W_ih0, b_ih0, gi_ptr);
    gru_rec<<<BQ / 4, 384, SMEM_REC>>>(gi_ptr, W_hh0, b_hh0, hist_ptr);
    // Layer 1 (gi buffer reused; hist overwritten with h2 after gi1 is built)
    gi_gemm<HQ><<<M_BLOCKS, 256, SMEM_GI128>>>(hist_ptr, W_ih1, b_ih1, gi_ptr);
    gru_rec<<<BQ / 4, 384, SMEM_REC>>>(gi_ptr, W_hh1, b_hh1, hist_ptr);
    // FC head
    fc_kernel<<<BQ, 128>>>(hist_ptr, W_fc, b_fc, out);
}